// round 14
// baseline (speedup 1.0000x reference)
#include <cuda_runtime.h>
#include <cstdint>

// ---------------------------------------------------------------------------
// Static scratch (no allocations allowed). N_NODES = 50000 in the reference.
// CAP = max binned in-degree: in-degree is Poisson(16); P(deg >= 96) ~ 1e-45.
// Both fill & reduce clamp to CAP (worst case wrong value, never a crash).
//
// g_deg starts zeroed (.bss). fill increments it; reduce consumes the count
// and writes 0 back, restoring the invariant for the next graph replay.
// g_bin slots >= k are never written (bss zero) -> reading them yields node 0,
// a valid row; prefetches of those rows are never consumed.
// ---------------------------------------------------------------------------
#define MAXN 50048
#define CAP  96
#define NPB  8        // nodes per block = 1 per warp, 8 warps
#define NSTG 8        // cp.async pipeline stages per warp

__device__ int g_deg[MAXN];
__device__ int g_bin[MAXN * CAP];   // ~19.2 MB: src ids grouped by dst

// ---------------------------------------------------------------------------
// Kernel 1: bin edges by destination. 4 edges per thread via int4 loads.
// ---------------------------------------------------------------------------
__global__ void fill_kernel4(const int4* __restrict__ src4,
                             const int4* __restrict__ dst4,
                             int n4, int n_nodes) {
    int i = blockIdx.x * blockDim.x + threadIdx.x;
    if (i >= n4) return;
    int4 s = __ldg(src4 + i);
    int4 t = __ldg(dst4 + i);

    #pragma unroll
    for (int u = 0; u < 4; u++) {
        int ss = (u == 0) ? s.x : (u == 1) ? s.y : (u == 2) ? s.z : s.w;
        int tt = (u == 0) ? t.x : (u == 1) ? t.y : (u == 2) ? t.z : t.w;
        if ((unsigned)ss >= (unsigned)n_nodes || (unsigned)tt >= (unsigned)n_nodes)
            continue;
        int pos = atomicAdd(&g_deg[tt], 1);
        if (pos < CAP) g_bin[tt * CAP + pos] = ss;
    }
}

__global__ void fill_kernel_tail(const int* __restrict__ src,
                                 const int* __restrict__ dst,
                                 int e0, int n_edges, int n_nodes) {
    int e = e0 + blockIdx.x * blockDim.x + threadIdx.x;
    if (e >= n_edges) return;
    int s = __ldg(src + e);
    int t = __ldg(dst + e);
    if ((unsigned)s >= (unsigned)n_nodes || (unsigned)t >= (unsigned)n_nodes) return;
    int pos = atomicAdd(&g_deg[t], 1);
    if (pos < CAP) g_bin[t * CAP + pos] = s;
}

// ---------------------------------------------------------------------------
// Kernel 2: warp-per-node gather-reduce + mean with a cp.async smem pipeline.
// R12/R13 showed a conserved occ x register-MLP budget (~208 outstanding
// loads/SM) -> latency plateau at ~37us. cp.async decouples MLP from
// registers: 8-stage per-warp ring of feature rows in smem, each lane copies
// and later consumes ONLY its own 16B slot (own-thread visibility after
// wait_group; no syncwarp needed). Loop runs exactly k iterations with no
// masks or branches; prefetches past k fetch padded row 0 and are dropped.
// Lanes 24..31 copy a duplicate of chunk 0 and never store.
// ---------------------------------------------------------------------------
__global__ void reduce_kernel(const float* __restrict__ feat,
                              float* __restrict__ out,
                              int n_nodes) {
    __shared__ float4 s_buf[NPB][NSTG][32];   // 32 KB ring buffers
    __shared__ int    s_ids[NPB * CAP];       // 3 KB ids
    __shared__ int    s_k[NPB];

    const int t     = threadIdx.x;
    const int node0 = blockIdx.x * NPB;

    // Stage degrees (consume + reset for next graph replay).
    if (t < NPB) {
        int n = node0 + t;
        int k = 0;
        if (n < n_nodes) {
            k = g_deg[n];
            g_deg[n] = 0;
            k = k < CAP ? k : CAP;
        }
        s_k[t] = k;
    }
    __syncthreads();

    // Stage src ids; pad slots >= k with 0 (valid row, never consumed).
    for (int idx = t; idx < NPB * CAP; idx += 256) {
        int nl  = idx / CAP;
        int pos = idx - nl * CAP;
        s_ids[idx] = (pos < s_k[nl]) ? __ldg(g_bin + (node0 + nl) * CAP + pos) : 0;
    }
    __syncthreads();

    const int lane  = t & 31;
    const int warp  = t >> 5;
    const int node  = node0 + warp;
    const int chunk = lane < 24 ? lane : 0;   // safe duplicate for tail lanes

    const int  k   = warp < NPB ? s_k[warp] : 0;
    const int* ids = s_ids + warp * CAP;
    const float4* feat4 = reinterpret_cast<const float4*>(feat);

    // Per-lane smem slot base inside this warp's ring.
    uint32_t slot0 = (uint32_t)__cvta_generic_to_shared(&s_buf[warp][0][lane]);

    // Prologue: prefetch rows 0..NSTG-1 (ids padded -> always valid).
    #pragma unroll
    for (int d = 0; d < NSTG; d++) {
        int sid = ids[d];
        const float4* g = feat4 + (size_t)sid * 24 + chunk;
        uint32_t saddr = slot0 + d * (32 * 16);
        asm volatile("cp.async.cg.shared.global [%0], [%1], 16;"
                     :: "r"(saddr), "l"(g));
        asm volatile("cp.async.commit_group;");
    }

    float4 acc = make_float4(0.f, 0.f, 0.f, 0.f);
    for (int j = 0; j < k; j++) {
        asm volatile("cp.async.wait_group %0;" :: "n"(NSTG - 1) : "memory");
        const int st = j & (NSTG - 1);
        float4 v = s_buf[warp][st][lane];     // own slot: no syncwarp needed
        acc.x += v.x; acc.y += v.y; acc.z += v.z; acc.w += v.w;

        // Refill stage st with row j+NSTG (clamped into padded id range).
        int jn = j + NSTG;
        jn = jn < CAP ? jn : 0;
        int sid = ids[jn];
        const float4* g = feat4 + (size_t)sid * 24 + chunk;
        uint32_t saddr = slot0 + st * (32 * 16);
        asm volatile("cp.async.cg.shared.global [%0], [%1], 16;"
                     :: "r"(saddr), "l"(g));
        asm volatile("cp.async.commit_group;");
    }
    // Drain outstanding copies before the CTA can exit / smem is reused.
    asm volatile("cp.async.wait_all;" ::: "memory");

    if (lane < 24 && node < n_nodes) {
        const float inv = 1.0f / fmaxf((float)k, 1.0f);
        reinterpret_cast<float4*>(out)[(size_t)node * 24 + lane] =
            make_float4(acc.x * inv, acc.y * inv, acc.z * inv, acc.w * inv);
    }
}

// ---------------------------------------------------------------------------
// Launch. Inputs (metadata order): feature f32 [N*96], src i32 [E], dst i32 [E].
// Output: f32 [N*96].
// ---------------------------------------------------------------------------
extern "C" void kernel_launch(void* const* d_in, const int* in_sizes, int n_in,
                              void* d_out, int out_size) {
    const float* feat = (const float*)d_in[0];
    const int*   src  = (const int*)d_in[1];
    const int*   dst  = (const int*)d_in[2];
    float*       out  = (float*)d_out;

    const int n_nodes = in_sizes[0] / 96;
    const int n_edges = in_sizes[1];
    const int n4      = n_edges / 4;
    const int tail    = n_edges - n4 * 4;

    {
        const int threads = 256;
        if (n4 > 0)
            fill_kernel4<<<(n4 + threads - 1) / threads, threads>>>(
                (const int4*)src, (const int4*)dst, n4, n_nodes);
        if (tail > 0)
            fill_kernel_tail<<<1, 128>>>(src, dst, n4 * 4, n_edges, n_nodes);
    }
    {
        const int blocks = (n_nodes + NPB - 1) / NPB;   // 6250 for N=50000
        reduce_kernel<<<blocks, 256>>>(feat, out, n_nodes);
    }
}

// round 15
// speedup vs baseline: 13.9900x; 13.9900x over previous
#include <cuda_runtime.h>

// ---------------------------------------------------------------------------
// Static scratch (no allocations allowed). N_NODES = 50000 in the reference.
// CAP = max binned in-degree: in-degree is Poisson(16); P(deg >= 96) ~ 1e-45.
// Both fill & reduce clamp to CAP (worst case wrong value, never a crash).
//
// g_deg starts zeroed (.bss). fill increments it; reduce consumes the count
// and writes 0 back, restoring the invariant for the next graph replay.
// g_bin slots >= k are never written (bss zero) -> reading them yields node 0,
// a valid row, never accumulated (exact loop bounds).
// ---------------------------------------------------------------------------
#define MAXN 50048
#define CAP  96
#define NPB  16      // nodes per block (2 per warp, 8 warps)

__device__ int g_deg[MAXN];
__device__ int g_bin[MAXN * CAP];   // ~19.2 MB: src ids grouped by dst

// ---------------------------------------------------------------------------
// Kernel 1: bin edges by destination. 4 edges per thread via int4 loads.
// ---------------------------------------------------------------------------
__global__ void fill_kernel4(const int4* __restrict__ src4,
                             const int4* __restrict__ dst4,
                             int n4, int n_nodes) {
    int i = blockIdx.x * blockDim.x + threadIdx.x;
    if (i >= n4) return;
    int4 s = __ldg(src4 + i);
    int4 t = __ldg(dst4 + i);

    #pragma unroll
    for (int u = 0; u < 4; u++) {
        int ss = (u == 0) ? s.x : (u == 1) ? s.y : (u == 2) ? s.z : s.w;
        int tt = (u == 0) ? t.x : (u == 1) ? t.y : (u == 2) ? t.z : t.w;
        if ((unsigned)ss >= (unsigned)n_nodes || (unsigned)tt >= (unsigned)n_nodes)
            continue;
        int pos = atomicAdd(&g_deg[tt], 1);
        if (pos < CAP) g_bin[tt * CAP + pos] = ss;
    }
}

__global__ void fill_kernel_tail(const int* __restrict__ src,
                                 const int* __restrict__ dst,
                                 int e0, int n_edges, int n_nodes) {
    int e = e0 + blockIdx.x * blockDim.x + threadIdx.x;
    if (e >= n_edges) return;
    int s = __ldg(src + e);
    int t = __ldg(dst + e);
    if ((unsigned)s >= (unsigned)n_nodes || (unsigned)t >= (unsigned)n_nodes) return;
    int pos = atomicAdd(&g_deg[t], 1);
    if (pos < CAP) g_bin[t * CAP + pos] = s;
}

// ---------------------------------------------------------------------------
// Kernel 2: warp-per-2-nodes gather-reduce + mean (R12 layout, split loops).
// R12 measured: occ 81%, issue 45%, reduce 37.1us with masked max(k0,k1)
// loop. This version removes the ~14% wasted masked loads and the 2 FSELs
// per iteration: main loop runs min(k0,k1) with BOTH streams unmasked; a
// warp-uniform tail loop finishes the longer stream. cp.async path (R14)
// measured 19x worse - register/LDG pipelining is the right mechanism here.
// Lanes 24..31 load chunk 0 (valid dup) and never store.
// ---------------------------------------------------------------------------
__global__ void reduce_kernel(const float* __restrict__ feat,
                              float* __restrict__ out,
                              int n_nodes) {
    __shared__ int s_ids[NPB * CAP];
    __shared__ int s_k[NPB];

    const int t     = threadIdx.x;
    const int node0 = blockIdx.x * NPB;

    // Stage degrees (consume + reset for next graph replay).
    if (t < NPB) {
        int n = node0 + t;
        int k = 0;
        if (n < n_nodes) {
            k = g_deg[n];
            g_deg[n] = 0;
            k = k < CAP ? k : CAP;
        }
        s_k[t] = k;
    }
    __syncthreads();

    // Stage src ids; pad slots >= k with 0 (valid row, never accumulated).
    for (int idx = t; idx < NPB * CAP; idx += 256) {
        int nl  = idx / CAP;
        int pos = idx - nl * CAP;
        s_ids[idx] = (pos < s_k[nl]) ? __ldg(g_bin + (node0 + nl) * CAP + pos) : 0;
    }
    __syncthreads();

    const int lane  = t & 31;
    const int warp  = t >> 5;
    const int na    = node0 + 2 * warp;      // first node of this warp
    const int nb    = na + 1;                // second node
    const int chunk = lane < 24 ? lane : 0;  // safe duplicate for tail lanes

    const int ka = s_k[2 * warp];
    const int kb = s_k[2 * warp + 1];
    const int kmin = ka < kb ? ka : kb;
    const int kmax = ka > kb ? ka : kb;

    const int* idsa = s_ids + (2 * warp) * CAP;
    const int* idsb = idsa + CAP;
    const float4* feat4 = reinterpret_cast<const float4*>(feat);

    float4 acca = make_float4(0.f, 0.f, 0.f, 0.f);
    float4 accb = make_float4(0.f, 0.f, 0.f, 0.f);

    // Main loop: both streams live, no masks, no wasted loads.
    #pragma unroll 4
    for (int j = 0; j < kmin; j++) {
        int sa = idsa[j];                    // affine LDS broadcasts
        int sb = idsb[j];
        float4 va = __ldg(feat4 + (size_t)sa * 24 + chunk);
        float4 vb = __ldg(feat4 + (size_t)sb * 24 + chunk);
        acca.x += va.x; acca.y += va.y; acca.z += va.z; acca.w += va.w;
        accb.x += vb.x; accb.y += vb.y; accb.z += vb.z; accb.w += vb.w;
    }

    // Tail: finish the longer stream (warp-uniform branch, no divergence).
    {
        const int* idst = (ka > kb) ? idsa : idsb;
        float4 at = make_float4(0.f, 0.f, 0.f, 0.f);
        #pragma unroll 4
        for (int j = kmin; j < kmax; j++) {
            int st = idst[j];
            float4 v = __ldg(feat4 + (size_t)st * 24 + chunk);
            at.x += v.x; at.y += v.y; at.z += v.z; at.w += v.w;
        }
        if (ka > kb) {
            acca.x += at.x; acca.y += at.y; acca.z += at.z; acca.w += at.w;
        } else {
            accb.x += at.x; accb.y += at.y; accb.z += at.z; accb.w += at.w;
        }
    }

    if (lane < 24) {
        if (na < n_nodes) {
            const float inv = 1.0f / fmaxf((float)ka, 1.0f);
            reinterpret_cast<float4*>(out)[(size_t)na * 24 + lane] =
                make_float4(acca.x * inv, acca.y * inv, acca.z * inv, acca.w * inv);
        }
        if (nb < n_nodes) {
            const float inv = 1.0f / fmaxf((float)kb, 1.0f);
            reinterpret_cast<float4*>(out)[(size_t)nb * 24 + lane] =
                make_float4(accb.x * inv, accb.y * inv, accb.z * inv, accb.w * inv);
        }
    }
}

// ---------------------------------------------------------------------------
// Launch. Inputs (metadata order): feature f32 [N*96], src i32 [E], dst i32 [E].
// Output: f32 [N*96].
// ---------------------------------------------------------------------------
extern "C" void kernel_launch(void* const* d_in, const int* in_sizes, int n_in,
                              void* d_out, int out_size) {
    const float* feat = (const float*)d_in[0];
    const int*   src  = (const int*)d_in[1];
    const int*   dst  = (const int*)d_in[2];
    float*       out  = (float*)d_out;

    const int n_nodes = in_sizes[0] / 96;
    const int n_edges = in_sizes[1];
    const int n4      = n_edges / 4;
    const int tail    = n_edges - n4 * 4;

    {
        const int threads = 256;
        if (n4 > 0)
            fill_kernel4<<<(n4 + threads - 1) / threads, threads>>>(
                (const int4*)src, (const int4*)dst, n4, n_nodes);
        if (tail > 0)
            fill_kernel_tail<<<1, 128>>>(src, dst, n4 * 4, n_edges, n_nodes);
    }
    {
        const int blocks = (n_nodes + NPB - 1) / NPB;   // 3125 for N=50000
        reduce_kernel<<<blocks, 256>>>(feat, out, n_nodes);
    }
}